// round 10
// baseline (speedup 1.0000x reference)
#include <cuda_runtime.h>
#include <math.h>
#include <stdint.h>

#define SS   16
#define NG   128
#define NZ   254          // output length along z = 2*(128-1)
#define DIN  3072
#define DH   1024
#define DOUT 49152
#define PI_D 3.14159265358979323846

#define TILE_ROWS   8
#define TILE_BYTES  (TILE_ROWS * DH * 4)     // 32 KB (8 contiguous rows)
#define STAGE_BYTES (2 * TILE_BYTES)         // 64 KB (W2r tile + W2i tile)
#define MLP2_SMEM   (2 * STAGE_BYTES)        // double buffer: 128 KB

// ---------------- scratch (device globals; no allocations) ----------------
__device__ __align__(16) float2 g_Cy[3 * 128 * 16];      // y-DFT of boundary fields
__device__ __align__(16) float  g_xr[DIN];               // MLP input (real)
__device__             float   g_h [DH];                 // hidden layer
__device__ __align__(16) float2 g_o [DOUT];              // complex GEMV output (12,16,16,16)
__device__ __align__(16) float  g_Y1r[12 * 32 * 128 * 16]; // y-transform, real plane
__device__ __align__(16) float  g_Y1i[12 * 32 * 128 * 16]; // y-transform, imag plane
__device__ __align__(16) float  g_Fr [12 * 128 * 128 * 16]; // x-transform, real plane
__device__ __align__(16) float  g_Fi [12 * 128 * 128 * 16]; // x-transform, imag plane
__device__             float2  g_tw128[128];             // e^{+2πi t/128}
__device__ __align__(16) float2 g_twc[8 * 128];          // (w cos) pairs: [k][zp] -> kz=2k,2k+1
__device__ __align__(16) float2 g_tws[8 * 128];          // (w sin) pairs

// ---------------- packed f32x2 helpers ----------------
__device__ __forceinline__ unsigned long long fma2(unsigned long long a,
                                                   unsigned long long b,
                                                   unsigned long long c) {
    unsigned long long d;
    asm("fma.rn.f32x2 %0, %1, %2, %3;" : "=l"(d) : "l"(a), "l"(b), "l"(c));
    return d;
}
__device__ __forceinline__ float f2lo(unsigned long long u) {
    return __uint_as_float((unsigned int)u);
}
__device__ __forceinline__ float f2hi(unsigned long long u) {
    return __uint_as_float((unsigned int)(u >> 32));
}
__device__ __forceinline__ unsigned long long pack2(float a, float b) {
    return (unsigned long long)__float_as_uint(a) |
           ((unsigned long long)__float_as_uint(b) << 32);
}

// ---------------- mbarrier / bulk-async helpers ----------------
__device__ __forceinline__ uint32_t smem_u32(const void* p) {
    uint32_t a;
    asm("{ .reg .u64 t; cvta.to.shared.u64 t, %1; cvt.u32.u64 %0, t; }"
        : "=r"(a) : "l"(p));
    return a;
}
__device__ __forceinline__ void mbar_init(uint32_t mbar, uint32_t count) {
    asm volatile("mbarrier.init.shared.b64 [%0], %1;" :: "r"(mbar), "r"(count)
                 : "memory");
}
__device__ __forceinline__ void mbar_expect_tx(uint32_t mbar, uint32_t bytes) {
    asm volatile("mbarrier.arrive.expect_tx.shared.b64 _, [%0], %1;"
                 :: "r"(mbar), "r"(bytes) : "memory");
}
__device__ __forceinline__ void mbar_wait(uint32_t mbar, uint32_t phase) {
    asm volatile(
        "{\n\t"
        ".reg .pred P1;\n\t"
        "WAIT_LOOP_%=:\n\t"
        "mbarrier.try_wait.parity.acquire.cta.shared::cta.b64 P1, [%0], %1, 0x989680;\n\t"
        "@P1 bra.uni WAIT_DONE_%=;\n\t"
        "bra.uni WAIT_LOOP_%=;\n\t"
        "WAIT_DONE_%=:\n\t"
        "}"
        :: "r"(mbar), "r"(phase) : "memory");
}
__device__ __forceinline__ void bulk_g2s(uint32_t dst, const void* src,
                                         uint32_t bytes, uint32_t mbar) {
    asm volatile(
        "cp.async.bulk.shared::cta.global.mbarrier::complete_tx::bytes "
        "[%0], [%1], %2, [%3];"
        :: "r"(dst), "l"(src), "r"(bytes), "r"(mbar) : "memory");
}

// ---------------- K0: twiddle tables (double precision, deterministic) ----
__global__ void k_init_tw() {
    int i = blockIdx.x * blockDim.x + threadIdx.x;
    if (i < 128) {
        double a = 2.0 * PI_D * (double)i / 128.0;
        g_tw128[i] = make_float2((float)cos(a), (float)sin(a));
    }
    if (i < 8 * 128) {
        int k = i >> 7, zp = i & 127;
        double n3 = (double)NG * (double)NG * (double)NZ;
        int kz0 = 2 * k, kz1 = 2 * k + 1;
        double w0 = (kz0 == 0 ? 1.0 : 2.0) / n3;
        double w1 = 2.0 / n3;
        double a0 = 2.0 * PI_D * (double)(kz0 * zp) / (double)NZ;
        double a1 = 2.0 * PI_D * (double)(kz1 * zp) / (double)NZ;
        g_twc[i] = make_float2((float)(w0 * cos(a0)), (float)(w1 * cos(a1)));
        g_tws[i] = make_float2((float)(w0 * sin(a0)), (float)(w1 * sin(a1)));
    }
}

// ---------------- K1a: forward DFT along y (16 modes) ----------------
__global__ void k_dft_y(const float* __restrict__ Br, const float* __restrict__ Bp,
                        const float* __restrict__ Bt) {
    int f = blockIdx.x >> 7;
    int x = blockIdx.x & 127;
    const float* src = (f == 0) ? Bp : (f == 1) ? Bt : Br;
    float sgn = (f == 1) ? -1.f : 1.f;
    __shared__ float  row[128];
    __shared__ float2 tw[128];
    int t = threadIdx.x;
    row[t] = sgn * src[x * 128 + t];
    tw[t]  = g_tw128[t];
    __syncthreads();
    if (t < 16) {
        float re = 0.f, im = 0.f;
        #pragma unroll 8
        for (int y = 0; y < 128; y++) {
            float2 w = tw[(t * y) & 127];
            float v = row[y];
            re += v * w.x;
            im -= v * w.y;
        }
        g_Cy[(f * 128 + x) * 16 + t] = make_float2(re, im);
    }
}

// ---------------- K1b: forward DFT along x (32 modes) -> xr --------------
__global__ __launch_bounds__(256) void k_dft_x() {
    int b = blockIdx.x;           // 0..95  (f*32 + kxi)
    int f = b / 32, kxi = b % 32;
    __shared__ float2 tw[128];
    __shared__ float2 red[256];
    int t = threadIdx.x;
    if (t < 128) tw[t] = g_tw128[t];
    __syncthreads();
    int ky = t & 15, xc = t >> 4;           // xc: 0..15, 8 x's each
    int kxe = (kxi < 16) ? kxi : (kxi + 96);
    float re = 0.f, im = 0.f;
    #pragma unroll
    for (int j = 0; j < 8; j++) {
        int x = xc * 8 + j;
        float2 c = g_Cy[(f * 128 + x) * 16 + ky];
        float2 w = tw[(kxe * x) & 127];
        re += c.x * w.x + c.y * w.y;
        im += c.y * w.x - c.x * w.y;
    }
    red[t] = make_float2(re, im);
    __syncthreads();
    #pragma unroll
    for (int s = 8; s >= 1; s >>= 1) {
        if (xc < s) {
            red[t].x += red[t + 16 * s].x;
            red[t].y += red[t + 16 * s].y;
        }
        __syncthreads();
    }
    if (t < 16) {
        int seg = f * 512 + (kxi >= 16 ? 256 : 0) + (kxi & 15) * 16 + t;
        g_xr[seg]        = red[t].x;
        g_xr[1536 + seg] = red[t].y;
    }
}

// ---------------- K2: hidden GEMV + sigmoid (no staging, direct L2) ------
__global__ __launch_bounds__(256) void k_mlp1(const float* __restrict__ W1,
                                              const float* __restrict__ b1) {
    __shared__ float part[8];
    int t = threadIdx.x;
    int w = t >> 5, lane = t & 31;
    int row = blockIdx.x * 2 + (w >> 2);    // 2 rows per block
    int q   = w & 3;                        // quarter of the row
    const float4* wr = (const float4*)(W1 + (size_t)row * DIN) + q * 192;
    const float4* xv = ((const float4*)g_xr) + q * 192;
    float acc = 0.f;
    #pragma unroll
    for (int k = 0; k < 6; k++) {
        int j = lane + 32 * k;
        float4 a = wr[j];
        float4 x4 = __ldg(xv + j);
        acc += a.x * x4.x + a.y * x4.y + a.z * x4.z + a.w * x4.w;
    }
    #pragma unroll
    for (int o = 16; o > 0; o >>= 1)
        acc += __shfl_xor_sync(0xffffffffu, acc, o);
    if (lane == 0) part[w] = acc;
    __syncthreads();
    if (t < 2) {
        int r2 = blockIdx.x * 2 + t;
        float v = part[t * 4] + part[t * 4 + 1] + part[t * 4 + 2] + part[t * 4 + 3]
                + b1[r2];
        g_h[r2] = 1.f / (1.f + expf(-v));
    }
}

// ---------------- K3: complex GEMV via bulk-async double buffer -----------
// Block handles 4 tiles of 8 rows. Stage = 8 rows W2r + 8 rows W2i (64 KB),
// fetched by two cp.async.bulk into one mbarrier (expect_tx = 64 KB).
__global__ __launch_bounds__(256) void k_mlp2(int row0,
                                              const float* __restrict__ W2r,
                                              const float* __restrict__ W2i,
                                              const float* __restrict__ b2r,
                                              const float* __restrict__ b2i) {
    extern __shared__ __align__(16) unsigned char sbuf[];   // 2 x 64 KB
    __shared__ __align__(16) float sh[DH];
    __shared__ __align__(8) unsigned long long mbar_store[2];
    int t = threadIdx.x;
    for (int i = t; i < DH; i += 256) sh[i] = g_h[i];
    uint32_t mb0 = smem_u32(&mbar_store[0]);
    uint32_t mb1 = smem_u32(&mbar_store[1]);
    uint32_t sb  = smem_u32(sbuf);
    if (t == 0) { mbar_init(mb0, 1); mbar_init(mb1, 1); }
    __syncthreads();

    int tile0 = blockIdx.x * 4;                 // 4 tiles per block
    const char* srcR = (const char*)W2r + (size_t)(row0 + tile0 * TILE_ROWS) * DH * 4;
    const char* srcI = (const char*)W2i + (size_t)(row0 + tile0 * TILE_ROWS) * DH * 4;

    if (t == 0) {
        mbar_expect_tx(mb0, STAGE_BYTES);
        bulk_g2s(sb,              srcR,              TILE_BYTES, mb0);
        bulk_g2s(sb + TILE_BYTES, srcI,              TILE_BYTES, mb0);
        mbar_expect_tx(mb1, STAGE_BYTES);
        bulk_g2s(sb + STAGE_BYTES,              srcR + TILE_BYTES, TILE_BYTES, mb1);
        bulk_g2s(sb + STAGE_BYTES + TILE_BYTES, srcI + TILE_BYTES, TILE_BYTES, mb1);
    }

    int w = t >> 5, lane = t & 31;
    int ph[2] = {0, 0};
    const float4* hv = (const float4*)sh;

    #pragma unroll
    for (int j = 0; j < 4; j++) {
        int p = j & 1;
        mbar_wait(p ? mb1 : mb0, ph[p]);
        ph[p] ^= 1;

        const float4* wr4 = (const float4*)(sbuf + p * STAGE_BYTES) + w * 256;
        const float4* wi4 = (const float4*)(sbuf + p * STAGE_BYTES + TILE_BYTES) + w * 256;
        float ar = 0.f, ai = 0.f;
        #pragma unroll
        for (int k = 0; k < 8; k++) {
            int j2 = lane + 32 * k;
            float4 h4 = hv[j2];
            float4 r4 = wr4[j2];
            float4 i4 = wi4[j2];
            ar += r4.x * h4.x + r4.y * h4.y + r4.z * h4.z + r4.w * h4.w;
            ai += i4.x * h4.x + i4.y * h4.y + i4.z * h4.z + i4.w * h4.w;
        }
        #pragma unroll
        for (int o = 16; o > 0; o >>= 1) {
            ar += __shfl_xor_sync(0xffffffffu, ar, o);
            ai += __shfl_xor_sync(0xffffffffu, ai, o);
        }
        int row = row0 + (tile0 + j) * TILE_ROWS + w;
        if (lane == 0) g_o[row] = make_float2(ar + b2r[row], ai + b2i[row]);

        __syncthreads();                    // all warps done reading buffer p
        if (j + 2 < 4 && t == 0) {          // refill buffer p with tile j+2
            uint32_t mb = p ? mb1 : mb0;
            mbar_expect_tx(mb, STAGE_BYTES);
            bulk_g2s(sb + p * STAGE_BYTES,
                     srcR + (size_t)(j + 2) * TILE_BYTES, TILE_BYTES, mb);
            bulk_g2s(sb + p * STAGE_BYTES + TILE_BYTES,
                     srcI + (size_t)(j + 2) * TILE_BYTES, TILE_BYTES, mb);
        }
    }
}

// ---------------- K4: inverse DFT along y (one field f) ------------------
__global__ void k_stage_y(int f) {
    int kxi = blockIdx.x;   // 0..31
    int yt  = blockIdx.y;   // 0..3
    __shared__ float2 Bsh[512];
    __shared__ float2 tw[128];
    int t = threadIdx.x;
    if (t < 128) tw[t] = g_tw128[t];
    int hx = (kxi >= 16) ? 1 : 0, p = kxi & 15;
    for (int e = t; e < 512; e += 256) {
        int kyi = e >> 4, kz = e & 15;
        int blk = f * 4 + hx * 2 + (kyi >= 16 ? 1 : 0);
        Bsh[e] = g_o[blk * 4096 + p * 256 + (kyi & 15) * 16 + kz];
    }
    __syncthreads();
    float mx = (kxi < 16) ? (float)kxi : (float)(kxi - 32);
    for (int it = t; it < 512; it += 256) {
        int y  = yt * 32 + (it >> 4);
        int kz = it & 15;
        float Sr = 0.f, Si = 0.f, Tr = 0.f, Ti = 0.f;
        #pragma unroll
        for (int kyi = 0; kyi < 32; kyi++) {
            int   kye = (kyi < 16) ? kyi : (kyi + 96);
            float my  = (kyi < 16) ? (float)kyi : (float)(kyi - 32);
            float2 w = tw[(kye * y) & 127];
            float2 B = Bsh[kyi * 16 + kz];
            Sr += B.x * w.x - B.y * w.y;
            Si += B.x * w.y + B.y * w.x;
            float br = -my * B.y, bi = my * B.x;   // i*my*B
            Tr += br * w.x - bi * w.y;
            Ti += br * w.y + bi * w.x;
        }
        int rest = (kxi * 128 + y) * 16 + kz;
        float fz = (float)kz;
        g_Y1r[ f          * 65536 + rest] = Sr;
        g_Y1i[ f          * 65536 + rest] = Si;
        g_Y1r[(3 + 3 * f) * 65536 + rest] = -mx * Si;
        g_Y1i[(3 + 3 * f) * 65536 + rest] =  mx * Sr;
        g_Y1r[(4 + 3 * f) * 65536 + rest] = Tr;
        g_Y1i[(4 + 3 * f) * 65536 + rest] = Ti;
        g_Y1r[(5 + 3 * f) * 65536 + rest] = -fz * Si;
        g_Y1i[(5 + 3 * f) * 65536 + rest] =  fz * Sr;
    }
}

// field f owns channels {f, 3f+3, 3f+4, 3f+5}
__device__ __forceinline__ int chan_of(int f, int by) {
    return (by == 0) ? f : (3 * f + 2 + by);
}

// ---------------- K5: inverse DFT along x (packed f32x2, SoA) ------------
__global__ __launch_bounds__(256) void k_stage_x(int f) {
    int y = blockIdx.x;                 // 0..127
    int c = chan_of(f, blockIdx.y);     // one of the field's 4 channels
    __shared__ __align__(16) float Yr[512];
    __shared__ __align__(16) float Yi[512];
    __shared__ float2 tw[128];
    int t = threadIdx.x;
    if (t < 128) tw[t] = g_tw128[t];
    for (int e = t; e < 512; e += 256) {
        int idx = c * 65536 + ((e >> 4) * 128 + y) * 16 + (e & 15);
        Yr[e] = g_Y1r[idx];
        Yi[e] = g_Y1i[idx];
    }
    __syncthreads();
    const unsigned long long* Yr2 = (const unsigned long long*)Yr; // [kxi*8+kzp]
    const unsigned long long* Yi2 = (const unsigned long long*)Yi;
    for (int it = t; it < 1024; it += 256) {
        int x = it >> 3, kzp = it & 7;
        unsigned long long r01 = 0ull, i01 = 0ull;
        #pragma unroll
        for (int kxi = 0; kxi < 32; kxi++) {
            int kxe = (kxi < 16) ? kxi : (kxi + 96);
            float2 w = tw[(kxe * x) & 127];
            unsigned long long wx2 = pack2(w.x,  w.x);
            unsigned long long wy2 = pack2(w.y,  w.y);
            unsigned long long wyn = pack2(-w.y, -w.y);
            unsigned long long vr = Yr2[kxi * 8 + kzp];
            unsigned long long vi = Yi2[kxi * 8 + kzp];
            r01 = fma2(vr, wx2, r01);
            r01 = fma2(vi, wyn, r01);
            i01 = fma2(vr, wy2, i01);
            i01 = fma2(vi, wx2, i01);
        }
        size_t base = ((size_t)(c * 128 + x) * 128 + y) * 8 + kzp;
        ((unsigned long long*)g_Fr)[base] = r01;
        ((unsigned long long*)g_Fi)[base] = i01;
    }
}

// ---------------- K6: final z-transform (Re), z-symmetry + f32x2 ---------
// A(z)=Σ Fr·w·cos, B(z)=Σ Fi·w·sin ; out(z)=A−B, out(254−z)=A+B
__global__ __launch_bounds__(256) void k_stage_z(int f, float* __restrict__ out) {
    int x = blockIdx.x;                 // 0..127
    int c = chan_of(f, blockIdx.y);
    __shared__ __align__(16) float Fr[2048];   // [y][16 kz]
    __shared__ __align__(16) float Fi[2048];
    int t = threadIdx.x;
    {
        const float4* sr = (const float4*)(g_Fr + (size_t)(c * 128 + x) * 2048);
        const float4* si = (const float4*)(g_Fi + (size_t)(c * 128 + x) * 2048);
        float4* dr = (float4*)Fr;
        float4* di = (float4*)Fi;
        for (int e = t; e < 512; e += 256) { dr[e] = sr[e]; di[e] = si[e]; }
    }
    __syncthreads();
    int zp = t & 127, half = t >> 7;

    unsigned long long C[8], Sn[8];
    #pragma unroll
    for (int k = 0; k < 8; k++) {
        float2 cc = g_twc[k * 128 + zp];
        float2 ss = g_tws[k * 128 + zp];
        C [k] = pack2(cc.x, cc.y);
        Sn[k] = pack2(ss.x, ss.y);
    }
    const ulonglong2* Fr2 = (const ulonglong2*)Fr;  // [y*4 + q]
    const ulonglong2* Fi2 = (const ulonglong2*)Fi;
    float* obase = out + (size_t)((c * 128 + x) * 128) * NZ;
    for (int y = half; y < 128; y += 2) {
        unsigned long long a = 0ull, b = 0ull;
        #pragma unroll
        for (int q = 0; q < 4; q++) {
            ulonglong2 vr = Fr2[y * 4 + q];
            ulonglong2 vi = Fi2[y * 4 + q];
            a = fma2(vr.x, C [2 * q],     a);
            a = fma2(vr.y, C [2 * q + 1], a);
            b = fma2(vi.x, Sn[2 * q],     b);
            b = fma2(vi.y, Sn[2 * q + 1], b);
        }
        float A = f2lo(a) + f2hi(a);
        float B = f2lo(b) + f2hi(b);
        float* orow = obase + (size_t)y * NZ;
        orow[zp] = A - B;
        if (zp >= 1 && zp < 127) orow[254 - zp] = A + B;
    }
}

// ---------------- launch ----------------
extern "C" void kernel_launch(void* const* d_in, const int* in_sizes, int n_in,
                              void* d_out, int out_size) {
    const float* Br  = (const float*)d_in[0];
    const float* Bp  = (const float*)d_in[1];
    const float* Bt  = (const float*)d_in[2];
    const float* W1  = (const float*)d_in[3];
    const float* b1  = (const float*)d_in[4];
    const float* W2r = (const float*)d_in[5];
    const float* W2i = (const float*)d_in[6];
    const float* b2r = (const float*)d_in[7];
    const float* b2i = (const float*)d_in[8];
    float* out = (float*)d_out;

    // One-time resources (created on the first, uncaptured call; every call
    // issues the identical sequence of operations afterwards).
    static cudaStream_t s2 = 0;
    static cudaEvent_t evm[3];
    static cudaEvent_t evz = 0;
    if (!s2) {
        cudaStreamCreate(&s2);
        for (int g = 0; g < 3; g++)
            cudaEventCreateWithFlags(&evm[g], cudaEventDisableTiming);
        cudaEventCreateWithFlags(&evz, cudaEventDisableTiming);
        cudaFuncSetAttribute(k_mlp2, cudaFuncAttributeMaxDynamicSharedMemorySize,
                             MLP2_SMEM);
    }

    k_init_tw<<<16, 256>>>();
    k_dft_y  <<<384, 128>>>(Br, Bp, Bt);
    k_dft_x  <<<96, 256>>>();
    k_mlp1   <<<512, 256>>>(W1, b1);

    // chunked GEMV on s0, per-field tail (y->x->z) on s2, pipelined
    for (int f = 0; f < 3; f++) {
        k_mlp2<<<512, 256, MLP2_SMEM>>>(16384 * f, W2r, W2i, b2r, b2i);
        cudaEventRecord(evm[f], 0);
        cudaStreamWaitEvent(s2, evm[f], 0);
        k_stage_y<<<dim3(32, 4), 256, 0, s2>>>(f);
        k_stage_x<<<dim3(128, 4), 256, 0, s2>>>(f);
        k_stage_z<<<dim3(128, 4), 256, 0, s2>>>(f, out);
    }
    cudaEventRecord(evz, s2);
    cudaStreamWaitEvent(0, evz, 0);
}

// round 11
// speedup vs baseline: 1.1262x; 1.1262x over previous
#include <cuda_runtime.h>
#include <math.h>
#include <stdint.h>

#define SS   16
#define NG   128
#define NZ   254          // output length along z = 2*(128-1)
#define DIN  3072
#define DH   1024
#define DOUT 49152
#define PI_D 3.14159265358979323846

// ---------------- scratch (device globals; no allocations) ----------------
__device__ __align__(16) float2 g_Cy[3 * 128 * 16];      // y-DFT of boundary fields
__device__ __align__(16) float  g_xr[DIN];               // MLP input (real)
__device__             float   g_h [DH];                 // hidden layer
__device__ __align__(16) float2 g_o [DOUT];              // complex GEMV output (12,16,16,16)
__device__ __align__(16) float  g_Y1r[12 * 32 * 128 * 16]; // y-transform, real plane
__device__ __align__(16) float  g_Y1i[12 * 32 * 128 * 16]; // y-transform, imag plane
__device__             float2  g_tw128[128];             // e^{+2πi t/128}
__device__ __align__(16) float2 g_twc[8 * 128];          // (w cos) pairs: [k][zp] -> kz=2k,2k+1
__device__ __align__(16) float2 g_tws[8 * 128];          // (w sin) pairs

// ---------------- packed f32x2 helpers ----------------
__device__ __forceinline__ unsigned long long fma2(unsigned long long a,
                                                   unsigned long long b,
                                                   unsigned long long c) {
    unsigned long long d;
    asm("fma.rn.f32x2 %0, %1, %2, %3;" : "=l"(d) : "l"(a), "l"(b), "l"(c));
    return d;
}
__device__ __forceinline__ float f2lo(unsigned long long u) {
    return __uint_as_float((unsigned int)u);
}
__device__ __forceinline__ float f2hi(unsigned long long u) {
    return __uint_as_float((unsigned int)(u >> 32));
}
__device__ __forceinline__ unsigned long long pack2(float a, float b) {
    return (unsigned long long)__float_as_uint(a) |
           ((unsigned long long)__float_as_uint(b) << 32);
}

// ---------------- K0: twiddle tables (double precision, deterministic) ----
__global__ void k_init_tw() {
    int i = blockIdx.x * blockDim.x + threadIdx.x;
    if (i < 128) {
        double a = 2.0 * PI_D * (double)i / 128.0;
        g_tw128[i] = make_float2((float)cos(a), (float)sin(a));
    }
    if (i < 8 * 128) {
        int k = i >> 7, zp = i & 127;
        double n3 = (double)NG * (double)NG * (double)NZ;
        int kz0 = 2 * k, kz1 = 2 * k + 1;
        double w0 = (kz0 == 0 ? 1.0 : 2.0) / n3;
        double w1 = 2.0 / n3;
        double a0 = 2.0 * PI_D * (double)(kz0 * zp) / (double)NZ;
        double a1 = 2.0 * PI_D * (double)(kz1 * zp) / (double)NZ;
        g_twc[i] = make_float2((float)(w0 * cos(a0)), (float)(w1 * cos(a1)));
        g_tws[i] = make_float2((float)(w0 * sin(a0)), (float)(w1 * sin(a1)));
    }
}

// ---------------- K1a: forward DFT along y (16 modes) ----------------
__global__ void k_dft_y(const float* __restrict__ Br, const float* __restrict__ Bp,
                        const float* __restrict__ Bt) {
    int f = blockIdx.x >> 7;
    int x = blockIdx.x & 127;
    const float* src = (f == 0) ? Bp : (f == 1) ? Bt : Br;
    float sgn = (f == 1) ? -1.f : 1.f;
    __shared__ float  row[128];
    __shared__ float2 tw[128];
    int t = threadIdx.x;
    row[t] = sgn * src[x * 128 + t];
    tw[t]  = g_tw128[t];
    __syncthreads();
    if (t < 16) {
        float re = 0.f, im = 0.f;
        #pragma unroll 8
        for (int y = 0; y < 128; y++) {
            float2 w = tw[(t * y) & 127];
            float v = row[y];
            re += v * w.x;
            im -= v * w.y;
        }
        g_Cy[(f * 128 + x) * 16 + t] = make_float2(re, im);
    }
}

// ---------------- K1b: forward DFT along x (32 modes) -> xr --------------
__global__ __launch_bounds__(256) void k_dft_x() {
    int b = blockIdx.x;           // 0..95  (f*32 + kxi)
    int f = b / 32, kxi = b % 32;
    __shared__ float2 tw[128];
    __shared__ float2 red[256];
    int t = threadIdx.x;
    if (t < 128) tw[t] = g_tw128[t];
    __syncthreads();
    int ky = t & 15, xc = t >> 4;           // xc: 0..15, 8 x's each
    int kxe = (kxi < 16) ? kxi : (kxi + 96);
    float re = 0.f, im = 0.f;
    #pragma unroll
    for (int j = 0; j < 8; j++) {
        int x = xc * 8 + j;
        float2 c = g_Cy[(f * 128 + x) * 16 + ky];
        float2 w = tw[(kxe * x) & 127];
        re += c.x * w.x + c.y * w.y;
        im += c.y * w.x - c.x * w.y;
    }
    red[t] = make_float2(re, im);
    __syncthreads();
    #pragma unroll
    for (int s = 8; s >= 1; s >>= 1) {
        if (xc < s) {
            red[t].x += red[t + 16 * s].x;
            red[t].y += red[t + 16 * s].y;
        }
        __syncthreads();
    }
    if (t < 16) {
        int seg = f * 512 + (kxi >= 16 ? 256 : 0) + (kxi & 15) * 16 + t;
        g_xr[seg]        = red[t].x;
        g_xr[1536 + seg] = red[t].y;
    }
}

// ---------------- K2: hidden GEMV + sigmoid (no staging, direct L2) ------
__global__ __launch_bounds__(256) void k_mlp1(const float* __restrict__ W1,
                                              const float* __restrict__ b1) {
    __shared__ float part[8];
    int t = threadIdx.x;
    int w = t >> 5, lane = t & 31;
    int row = blockIdx.x * 2 + (w >> 2);    // 2 rows per block
    int q   = w & 3;                        // quarter of the row
    const float4* wr = (const float4*)(W1 + (size_t)row * DIN) + q * 192;
    const float4* xv = ((const float4*)g_xr) + q * 192;
    float acc = 0.f;
    #pragma unroll
    for (int k = 0; k < 6; k++) {
        int j = lane + 32 * k;
        float4 a = wr[j];
        float4 x4 = __ldg(xv + j);
        acc += a.x * x4.x + a.y * x4.y + a.z * x4.z + a.w * x4.w;
    }
    #pragma unroll
    for (int o = 16; o > 0; o >>= 1)
        acc += __shfl_xor_sync(0xffffffffu, acc, o);
    if (lane == 0) part[w] = acc;
    __syncthreads();
    if (t < 2) {
        int r2 = blockIdx.x * 2 + t;
        float v = part[t * 4] + part[t * 4 + 1] + part[t * 4 + 2] + part[t * 4 + 3]
                + b1[r2];
        g_h[r2] = 1.f / (1.f + expf(-v));
    }
}

// ---------------- K3: complex output GEMV, 2 rows per warp ---------------
__global__ __launch_bounds__(256) void k_mlp2(int row0,
                                              const float* __restrict__ W2r,
                                              const float* __restrict__ W2i,
                                              const float* __restrict__ b2r,
                                              const float* __restrict__ b2i) {
    __shared__ __align__(16) float sh[DH];
    int t = threadIdx.x;
    for (int i = t; i < DH; i += 256) sh[i] = g_h[i];
    __syncthreads();
    int w = t >> 5, lane = t & 31;
    int row = row0 + blockIdx.x * 16 + w * 2;
    const float4* wr0 = ((const float4*)W2r) + (size_t)row * 256;
    const float4* wi0 = ((const float4*)W2i) + (size_t)row * 256;
    const float4* wr1 = wr0 + 256;
    const float4* wi1 = wi0 + 256;
    const float4* hv = (const float4*)sh;
    float ar0 = 0.f, ai0 = 0.f, ar1 = 0.f, ai1 = 0.f;
    #pragma unroll
    for (int k = 0; k < 8; k++) {
        int j = lane + 32 * k;
        float4 h4 = hv[j];
        float4 a = __ldcs(wr0 + j);
        float4 b = __ldcs(wi0 + j);
        float4 c = __ldcs(wr1 + j);
        float4 d = __ldcs(wi1 + j);
        ar0 += a.x * h4.x + a.y * h4.y + a.z * h4.z + a.w * h4.w;
        ai0 += b.x * h4.x + b.y * h4.y + b.z * h4.z + b.w * h4.w;
        ar1 += c.x * h4.x + c.y * h4.y + c.z * h4.z + c.w * h4.w;
        ai1 += d.x * h4.x + d.y * h4.y + d.z * h4.z + d.w * h4.w;
    }
    #pragma unroll
    for (int o = 16; o > 0; o >>= 1) {
        ar0 += __shfl_xor_sync(0xffffffffu, ar0, o);
        ai0 += __shfl_xor_sync(0xffffffffu, ai0, o);
        ar1 += __shfl_xor_sync(0xffffffffu, ar1, o);
        ai1 += __shfl_xor_sync(0xffffffffu, ai1, o);
    }
    if (lane == 0) {
        g_o[row]     = make_float2(ar0 + b2r[row],     ai0 + b2i[row]);
        g_o[row + 1] = make_float2(ar1 + b2r[row + 1], ai1 + b2i[row + 1]);
    }
}

// ---------------- K4: inverse DFT along y (one field f) ------------------
__global__ void k_stage_y(int f) {
    int kxi = blockIdx.x;   // 0..31
    int yt  = blockIdx.y;   // 0..3
    __shared__ float2 Bsh[512];
    __shared__ float2 tw[128];
    int t = threadIdx.x;
    if (t < 128) tw[t] = g_tw128[t];
    int hx = (kxi >= 16) ? 1 : 0, p = kxi & 15;
    for (int e = t; e < 512; e += 256) {
        int kyi = e >> 4, kz = e & 15;
        int blk = f * 4 + hx * 2 + (kyi >= 16 ? 1 : 0);
        Bsh[e] = g_o[blk * 4096 + p * 256 + (kyi & 15) * 16 + kz];
    }
    __syncthreads();
    float mx = (kxi < 16) ? (float)kxi : (float)(kxi - 32);
    for (int it = t; it < 512; it += 256) {
        int y  = yt * 32 + (it >> 4);
        int kz = it & 15;
        float Sr = 0.f, Si = 0.f, Tr = 0.f, Ti = 0.f;
        #pragma unroll
        for (int kyi = 0; kyi < 32; kyi++) {
            int   kye = (kyi < 16) ? kyi : (kyi + 96);
            float my  = (kyi < 16) ? (float)kyi : (float)(kyi - 32);
            float2 w = tw[(kye * y) & 127];
            float2 B = Bsh[kyi * 16 + kz];
            Sr += B.x * w.x - B.y * w.y;
            Si += B.x * w.y + B.y * w.x;
            float br = -my * B.y, bi = my * B.x;   // i*my*B
            Tr += br * w.x - bi * w.y;
            Ti += br * w.y + bi * w.x;
        }
        int rest = (kxi * 128 + y) * 16 + kz;
        float fz = (float)kz;
        g_Y1r[ f          * 65536 + rest] = Sr;
        g_Y1i[ f          * 65536 + rest] = Si;
        g_Y1r[(3 + 3 * f) * 65536 + rest] = -mx * Si;
        g_Y1i[(3 + 3 * f) * 65536 + rest] =  mx * Sr;
        g_Y1r[(4 + 3 * f) * 65536 + rest] = Tr;
        g_Y1i[(4 + 3 * f) * 65536 + rest] = Ti;
        g_Y1r[(5 + 3 * f) * 65536 + rest] = -fz * Si;
        g_Y1i[(5 + 3 * f) * 65536 + rest] =  fz * Sr;
    }
}

// field f owns channels {f, 3f+3, 3f+4, 3f+5}
__device__ __forceinline__ int chan_of(int f, int by) {
    return (by == 0) ? f : (3 * f + 2 + by);
}

// ---------------- K5: FUSED x-DFT + z-transform ---------------------------
// Block = (c, y). Phase 1: F[x,kz] = Σ_kx Y1[c,kx,y,kz]·e^{+iθx} into smem.
// Phase 2: out[c,x,y,z] = Σ_kz Fr·w·cos + Fi·w·(-sin), with z-symmetry:
//          A - B at z=zp, A + B at z=254-zp. No gmem round-trip for F.
__global__ __launch_bounds__(256) void k_stage_xz(int f, float* __restrict__ out) {
    int y = blockIdx.x;                 // 0..127
    int c = chan_of(f, blockIdx.y);     // one of the field's 4 channels
    __shared__ __align__(16) float Yr[512];
    __shared__ __align__(16) float Yi[512];
    __shared__ __align__(16) float Frs[2048];   // [x][16 kz]
    __shared__ __align__(16) float Fis[2048];
    __shared__ float2 tw[128];
    int t = threadIdx.x;
    if (t < 128) tw[t] = g_tw128[t];
    for (int e = t; e < 512; e += 256) {
        int idx = c * 65536 + ((e >> 4) * 128 + y) * 16 + (e & 15);
        Yr[e] = g_Y1r[idx];
        Yi[e] = g_Y1i[idx];
    }
    __syncthreads();

    // Phase 1: x-DFT (packed f32x2 over kz pairs)
    const unsigned long long* Yr2 = (const unsigned long long*)Yr; // [kxi*8+kzp]
    const unsigned long long* Yi2 = (const unsigned long long*)Yi;
    unsigned long long* Fr2w = (unsigned long long*)Frs;           // [x*8+kzp]
    unsigned long long* Fi2w = (unsigned long long*)Fis;
    #pragma unroll
    for (int rep = 0; rep < 4; rep++) {
        int it = t + rep * 256;
        int x = it >> 3, kzp = it & 7;
        unsigned long long r01 = 0ull, i01 = 0ull;
        #pragma unroll
        for (int kxi = 0; kxi < 32; kxi++) {
            int kxe = (kxi < 16) ? kxi : (kxi + 96);
            float2 w = tw[(kxe * x) & 127];
            unsigned long long wx2 = pack2(w.x,  w.x);
            unsigned long long wy2 = pack2(w.y,  w.y);
            unsigned long long wyn = pack2(-w.y, -w.y);
            unsigned long long vr = Yr2[kxi * 8 + kzp];
            unsigned long long vi = Yi2[kxi * 8 + kzp];
            r01 = fma2(vr, wx2, r01);
            r01 = fma2(vi, wyn, r01);
            i01 = fma2(vr, wy2, i01);
            i01 = fma2(vi, wx2, i01);
        }
        Fr2w[x * 8 + kzp] = r01;
        Fi2w[x * 8 + kzp] = i01;
    }
    __syncthreads();

    // Phase 2: z-transform with symmetry
    int zp = t & 127, half = t >> 7;
    unsigned long long C[8], Sn[8];
    #pragma unroll
    for (int k = 0; k < 8; k++) {
        float2 cc = g_twc[k * 128 + zp];
        float2 ss = g_tws[k * 128 + zp];
        C [k] = pack2(cc.x, cc.y);
        Sn[k] = pack2(ss.x, ss.y);
    }
    const ulonglong2* Fr2 = (const ulonglong2*)Frs;  // [x*4 + q]
    const ulonglong2* Fi2 = (const ulonglong2*)Fis;
    float* obase = out + ((size_t)c * 128 * 128 + y) * NZ;
    for (int x = half; x < 128; x += 2) {
        unsigned long long a = 0ull, b = 0ull;
        #pragma unroll
        for (int q = 0; q < 4; q++) {
            ulonglong2 vr = Fr2[x * 4 + q];
            ulonglong2 vi = Fi2[x * 4 + q];
            a = fma2(vr.x, C [2 * q],     a);
            a = fma2(vr.y, C [2 * q + 1], a);
            b = fma2(vi.x, Sn[2 * q],     b);
            b = fma2(vi.y, Sn[2 * q + 1], b);
        }
        float A = f2lo(a) + f2hi(a);
        float B = f2lo(b) + f2hi(b);
        float* orow = obase + (size_t)x * (128 * NZ);
        orow[zp] = A - B;
        if (zp >= 1 && zp < 127) orow[254 - zp] = A + B;
    }
}

// ---------------- launch ----------------
extern "C" void kernel_launch(void* const* d_in, const int* in_sizes, int n_in,
                              void* d_out, int out_size) {
    const float* Br  = (const float*)d_in[0];
    const float* Bp  = (const float*)d_in[1];
    const float* Bt  = (const float*)d_in[2];
    const float* W1  = (const float*)d_in[3];
    const float* b1  = (const float*)d_in[4];
    const float* W2r = (const float*)d_in[5];
    const float* W2i = (const float*)d_in[6];
    const float* b2r = (const float*)d_in[7];
    const float* b2i = (const float*)d_in[8];
    float* out = (float*)d_out;

    // One-time resources (created on the first, uncaptured call; every call
    // issues the identical sequence of operations afterwards).
    static cudaStream_t s2 = 0;
    static cudaEvent_t evm[3];
    static cudaEvent_t evz = 0;
    if (!s2) {
        cudaStreamCreate(&s2);
        for (int g = 0; g < 3; g++)
            cudaEventCreateWithFlags(&evm[g], cudaEventDisableTiming);
        cudaEventCreateWithFlags(&evz, cudaEventDisableTiming);
    }

    k_init_tw<<<16, 256>>>();
    k_dft_y  <<<384, 128>>>(Br, Bp, Bt);
    k_dft_x  <<<96, 256>>>();
    k_mlp1   <<<512, 256>>>(W1, b1);

    // chunked GEMV on s0, per-field tail (y -> fused xz) on s2, pipelined
    for (int f = 0; f < 3; f++) {
        k_mlp2<<<1024, 256>>>(16384 * f, W2r, W2i, b2r, b2i);
        cudaEventRecord(evm[f], 0);
        cudaStreamWaitEvent(s2, evm[f], 0);
        k_stage_y <<<dim3(32, 4), 256, 0, s2>>>(f);
        k_stage_xz<<<dim3(128, 4), 256, 0, s2>>>(f, out);
    }
    cudaEventRecord(evz, s2);
    cudaStreamWaitEvent(0, evz, 0);
}